// round 1
// baseline (speedup 1.0000x reference)
#include <cuda_runtime.h>
#include <cuda_bf16.h>
#include <math.h>

// EntityLinker fused MLP over graph edges.
// edge_input = [h_i, h_j, |h_i-h_j|, h_i*h_j]  (K = 4H = 512)
// x1 = relu(edge_input @ W1 + b1)  [E,256]
// x2 = relu(x1 @ W2 + b2)          [E,128]
// out = x2 @ W3 + b3               [E,2]
//
// Strategy (round 1, fp32 CUDA cores):
//  - 32 edges per CTA, 256 threads.
//  - h_i/h_j gathered into smem (node table 25.6MB is L2-resident).
//  - Layer 1 computed in 4 K-segments (hi, hj, |diff|, prod) generated on the
//    fly from smem so we never materialize the 512-wide edge_input.
//  - Weights streamed directly from L2 via float4 LDG (655KB, fully L2-resident,
//    every warp-lane load coalesced). Activation smem reads are warp-broadcast
//    (conflict-free).
//  - x2 aliases the dead h_i region -> 64KB smem + 256B idx -> 3 CTAs/SM.

#define THREADS 256
#define M_TILE 32
#define H 128

#define OFF_HI  0
#define OFF_HJ  (M_TILE * H)              // 4096 floats
#define OFF_X1  (2 * M_TILE * H)          // 8192 floats, [32][256]
#define OFF_X2  0                         // alias over dead h_i, [32][128]
#define OFF_IDX (OFF_X1 + M_TILE * 256)   // 16384 floats
#define SMEM_FLOATS (OFF_IDX + 2 * M_TILE)

__global__ void __launch_bounds__(THREADS)
entity_linker_kernel(const float* __restrict__ node,
                     const int* __restrict__ src,
                     const int* __restrict__ dst,
                     const float* __restrict__ W1, const float* __restrict__ b1,
                     const float* __restrict__ W2, const float* __restrict__ b2,
                     const float* __restrict__ W3, const float* __restrict__ b3,
                     float* __restrict__ out, int E)
{
    extern __shared__ float smem[];
    float* s_hi = smem + OFF_HI;
    float* s_hj = smem + OFF_HJ;
    float* s_x1 = smem + OFF_X1;
    float* s_x2 = smem + OFF_X2;     // aliases s_hi (dead after layer 1)
    int*   s_idx = (int*)(smem + OFF_IDX); // [0..31]=src rows, [32..63]=dst rows

    const int tid = threadIdx.x;
    const int e0  = blockIdx.x * M_TILE;

    // ---- load edge indices for this tile ----
    if (tid < 2 * M_TILE) {
        int m = tid & (M_TILE - 1);
        int e = e0 + m;
        int idx = 0;
        if (e < E) idx = (tid < M_TILE) ? src[e] : dst[e];
        s_idx[tid] = idx;
    }
    __syncthreads();

    // ---- gather h_i / h_j rows (each warp fetches one full 512B row) ----
    {
        const float4* nd = (const float4*)node; // 32 float4 per row
        #pragma unroll
        for (int it = 0; it < (M_TILE * 64) / THREADS; it++) {
            int lin = tid + it * THREADS;
            int m   = lin >> 6;
            int r   = lin & 63;
            int isj = r >> 5;       // 0 = h_i, 1 = h_j
            int j   = r & 31;       // float4 index within row
            int row = s_idx[m + isj * M_TILE];
            float4 v = nd[row * 32 + j];
            float* dp = (isj ? s_hj : s_hi) + m * H + j * 4;
            *(float4*)dp = v;
        }
    }
    __syncthreads();

    const int tx = tid & 31;   // N-direction lane
    const int ty = tid >> 5;   // M-direction warp
    const int m0 = ty * 4;     // 4 edges per thread
    const int n0 = tx * 8;     // 8 layer-1 outputs per thread

    // =================== layer 1: [32,512] @ W1[512,256] ===================
    float acc[4][8];
    {
        float4 bb0 = __ldg((const float4*)(b1 + n0));
        float4 bb1 = __ldg((const float4*)(b1 + n0 + 4));
        #pragma unroll
        for (int i = 0; i < 4; i++) {
            acc[i][0] = bb0.x; acc[i][1] = bb0.y; acc[i][2] = bb0.z; acc[i][3] = bb0.w;
            acc[i][4] = bb1.x; acc[i][5] = bb1.y; acc[i][6] = bb1.z; acc[i][7] = bb1.w;
        }
    }

    #pragma unroll
    for (int seg = 0; seg < 4; seg++) {
        const float* Wseg = W1 + seg * (H * 256);
        #pragma unroll 2
        for (int k = 0; k < H; k++) {
            float a[4];
            #pragma unroll
            for (int i = 0; i < 4; i++) {
                float hi = s_hi[(m0 + i) * H + k];
                float hj = s_hj[(m0 + i) * H + k];
                a[i] = (seg == 0) ? hi
                     : (seg == 1) ? hj
                     : (seg == 2) ? fabsf(hi - hj)
                                  : hi * hj;
            }
            float4 w0 = __ldg((const float4*)(Wseg + k * 256 + n0));
            float4 w1 = __ldg((const float4*)(Wseg + k * 256 + n0 + 4));
            #pragma unroll
            for (int i = 0; i < 4; i++) {
                acc[i][0] += a[i] * w0.x; acc[i][1] += a[i] * w0.y;
                acc[i][2] += a[i] * w0.z; acc[i][3] += a[i] * w0.w;
                acc[i][4] += a[i] * w1.x; acc[i][5] += a[i] * w1.y;
                acc[i][6] += a[i] * w1.z; acc[i][7] += a[i] * w1.w;
            }
        }
    }

    // relu -> x1 smem
    #pragma unroll
    for (int i = 0; i < 4; i++) {
        float4 v0 = make_float4(fmaxf(acc[i][0], 0.f), fmaxf(acc[i][1], 0.f),
                                fmaxf(acc[i][2], 0.f), fmaxf(acc[i][3], 0.f));
        float4 v1 = make_float4(fmaxf(acc[i][4], 0.f), fmaxf(acc[i][5], 0.f),
                                fmaxf(acc[i][6], 0.f), fmaxf(acc[i][7], 0.f));
        *(float4*)(s_x1 + (m0 + i) * 256 + n0)     = v0;
        *(float4*)(s_x1 + (m0 + i) * 256 + n0 + 4) = v1;
    }
    __syncthreads();   // x1 visible; also: everyone done reading hi/hj

    // =================== layer 2: [32,256] @ W2[256,128] ===================
    const int n1 = tx * 4;
    float acc2[4][4];
    {
        float4 bb = __ldg((const float4*)(b2 + n1));
        #pragma unroll
        for (int i = 0; i < 4; i++) {
            acc2[i][0] = bb.x; acc2[i][1] = bb.y; acc2[i][2] = bb.z; acc2[i][3] = bb.w;
        }
    }
    #pragma unroll 2
    for (int k = 0; k < 256; k++) {
        float a[4];
        #pragma unroll
        for (int i = 0; i < 4; i++) a[i] = s_x1[(m0 + i) * 256 + k];
        float4 w = __ldg((const float4*)(W2 + k * 128 + n1));
        #pragma unroll
        for (int i = 0; i < 4; i++) {
            acc2[i][0] += a[i] * w.x; acc2[i][1] += a[i] * w.y;
            acc2[i][2] += a[i] * w.z; acc2[i][3] += a[i] * w.w;
        }
    }
    // relu -> x2 smem (aliased region; safe: hi/hj reads all completed before
    // the previous __syncthreads)
    #pragma unroll
    for (int i = 0; i < 4; i++) {
        float4 v = make_float4(fmaxf(acc2[i][0], 0.f), fmaxf(acc2[i][1], 0.f),
                               fmaxf(acc2[i][2], 0.f), fmaxf(acc2[i][3], 0.f));
        *(float4*)(s_x2 + (m0 + i) * H + n1) = v;
    }
    __syncthreads();

    // =================== layer 3: [32,128] @ W3[128,2] ===================
    {
        int m = tid >> 3;     // 32 edges, 8 threads each
        int g = tid & 7;
        int e = e0 + m;
        float c0 = 0.f, c1 = 0.f;
        const float* xr = s_x2 + m * H;
        #pragma unroll
        for (int k = g; k < H; k += 8) {
            float  v = xr[k];
            float2 w = __ldg((const float2*)(W3 + k * 2));
            c0 += v * w.x;
            c1 += v * w.y;
        }
        #pragma unroll
        for (int off = 4; off; off >>= 1) {
            c0 += __shfl_down_sync(0xffffffffu, c0, off, 8);
            c1 += __shfl_down_sync(0xffffffffu, c1, off, 8);
        }
        if (g == 0 && e < E) {
            out[e * 2 + 0] = c0 + __ldg(b3 + 0);
            out[e * 2 + 1] = c1 + __ldg(b3 + 1);
        }
    }
}

extern "C" void kernel_launch(void* const* d_in, const int* in_sizes, int n_in,
                              void* d_out, int out_size)
{
    const float* node = (const float*)d_in[0];
    const int*   src  = (const int*)  d_in[1];
    const int*   dst  = (const int*)  d_in[2];
    const float* W1   = (const float*)d_in[3];
    const float* b1   = (const float*)d_in[4];
    const float* W2   = (const float*)d_in[5];
    const float* b2   = (const float*)d_in[6];
    const float* W3   = (const float*)d_in[7];
    const float* b3   = (const float*)d_in[8];
    float* out = (float*)d_out;

    const int E = in_sizes[1];
    const int smem_bytes = SMEM_FLOATS * (int)sizeof(float);   // 65792 B

    cudaFuncSetAttribute(entity_linker_kernel,
                         cudaFuncAttributeMaxDynamicSharedMemorySize, smem_bytes);

    const int grid = (E + M_TILE - 1) / M_TILE;
    entity_linker_kernel<<<grid, THREADS, smem_bytes>>>(
        node, src, dst, W1, b1, W2, b2, W3, b3, out, E);
}

// round 6
// speedup vs baseline: 3.8662x; 3.8662x over previous
#include <cuda_runtime.h>
#include <cuda_bf16.h>
#include <math.h>
#include <stdint.h>

// EntityLinker via bf16 split-precision mma.sync (HMMA fallback path, base sm_103).
//
// Layer1: D1[128 x 256] = A[128 x 512] @ W1, A = [h_i | h_j | |diff| | prod]
// Layer2: D2[128 x 128] = relu(D1+b1) @ W2
// Layer3: out[128 x 2]  = relu(D2+b2) @ W3 + b3  (CUDA cores + shuffle reduce)
//
// Precision: x = x_hi(bf16) + x_lo(bf16 residual); 3 MMA terms
// (Ah@Bh + Al@Bh + Ah@Bl), fp32 accumulate inside mma.sync.
//
// Weights pre-packed fragment-major (by prep kernel) so B frags are plain
// LDG.64. A tiles staged in smem (padded rows, LDSM conflict-free) and read
// with ldmatrix.x4.

#define THREADS 256
#define MTILE 128

// smem layout (bytes)
#define A_HI   0u
#define A_LO   34816u          // 128 rows * 272B
#define RS_A   272u            // 128 bf16 + 8 pad  (272 % 128 == 16 -> LDSM ok)
#define X_HI   69632u
#define X_LO   137216u         // 128 rows * 528B
#define RS_X   528u            // 256 bf16 + 8 pad
#define STG_I  69632u          // fp32 h_i staging [128][132] (aliases X_HI)
#define STG_J  137216u         // fp32 h_j staging (aliases X_LO)
#define SMEM_BYTES 204800

// packed weights: W1 4seg x 8ks x 2wn x 16nt x 2part x 32lane x 8B = 512KB
//                 W2 16ks x 2wn x 8nt x 2part x 32lane x 8B = 128KB
__device__ __align__(256) unsigned char g_w1p[524288];
__device__ __align__(256) unsigned char g_w2p[131072];

// ---------------- helpers ----------------

__device__ __forceinline__ uint32_t smem_u32(const void* p) {
    uint32_t a;
    asm("{ .reg .u64 t; cvta.to.shared.u64 t, %1; cvt.u32.u64 %0, t; }"
        : "=r"(a) : "l"(p));
    return a;
}

__device__ __forceinline__ void split2(float a, float b, uint32_t& h, uint32_t& l) {
    __nv_bfloat162 hh = __floats2bfloat162_rn(a, b);
    h = *reinterpret_cast<uint32_t*>(&hh);
    __nv_bfloat162 ll = __floats2bfloat162_rn(a - __bfloat162float(hh.x),
                                              b - __bfloat162float(hh.y));
    l = *reinterpret_cast<uint32_t*>(&ll);
}

__device__ __forceinline__ void ldsm4(uint32_t* r, uint32_t addr) {
    asm volatile("ldmatrix.sync.aligned.m8n8.x4.shared.b16 {%0,%1,%2,%3}, [%4];"
                 : "=r"(r[0]), "=r"(r[1]), "=r"(r[2]), "=r"(r[3]) : "r"(addr));
}

__device__ __forceinline__ void hmma(float* d, const uint32_t* a, uint2 b) {
    asm volatile(
        "mma.sync.aligned.m16n8k16.row.col.f32.bf16.bf16.f32 "
        "{%0,%1,%2,%3}, {%4,%5,%6,%7}, {%8,%9}, {%0,%1,%2,%3};"
        : "+f"(d[0]), "+f"(d[1]), "+f"(d[2]), "+f"(d[3])
        : "r"(a[0]), "r"(a[1]), "r"(a[2]), "r"(a[3]), "r"(b.x), "r"(b.y));
}

// ---------------- prep: pack W1/W2 fragment-major, bf16 hi/lo ----------------

__global__ void prep_weights(const float* __restrict__ W1,
                             const float* __restrict__ W2) {
    int t = blockIdx.x * blockDim.x + threadIdx.x;
    if (t < 65536) {
        // W1 frag word: t = (site*32 + lane)*2 + reg, site = ((seg*8+ks)*2+wn)*16+nt
        int reg  = t & 1;
        int lane = (t >> 1) & 31;
        int site = t >> 6;
        int nt   = site & 15;
        int rest = site >> 4;           // (seg*8+ks)*2+wn
        int wn   = rest & 1;
        int ks   = (rest >> 1) & 7;
        int seg  = rest >> 4;
        int n  = wn * 128 + nt * 8 + (lane >> 2);
        int k0 = seg * 128 + ks * 16 + (lane & 3) * 2 + reg * 8;
        float w0 = W1[k0 * 256 + n];
        float w1 = W1[(k0 + 1) * 256 + n];
        uint32_t h, l;
        split2(w0, w1, h, l);
        size_t base = (size_t)site * 512 + lane * 8 + reg * 4;
        *(uint32_t*)(g_w1p + base)       = h;   // part 0 (hi)
        *(uint32_t*)(g_w1p + base + 256) = l;   // part 1 (lo)
    } else if (t < 65536 + 16384) {
        int u = t - 65536;
        int reg  = u & 1;
        int lane = (u >> 1) & 31;
        int site = u >> 6;              // (ks*2+wn)*8+nt
        int nt   = site & 7;
        int rest = site >> 3;
        int wn   = rest & 1;
        int ks   = rest >> 1;
        int n  = wn * 64 + nt * 8 + (lane >> 2);
        int k0 = ks * 16 + (lane & 3) * 2 + reg * 8;
        float w0 = W2[k0 * 128 + n];
        float w1 = W2[(k0 + 1) * 128 + n];
        uint32_t h, l;
        split2(w0, w1, h, l);
        size_t base = (size_t)site * 512 + lane * 8 + reg * 4;
        *(uint32_t*)(g_w2p + base)       = h;
        *(uint32_t*)(g_w2p + base + 256) = l;
    }
}

// ---------------- main kernel ----------------

__global__ void __launch_bounds__(THREADS, 1)
linker_hmma_kernel(const float* __restrict__ node,
                   const int* __restrict__ src, const int* __restrict__ dst,
                   const float* __restrict__ b1v, const float* __restrict__ b2v,
                   const float* __restrict__ W3, const float* __restrict__ b3,
                   float* __restrict__ out, int E)
{
    extern __shared__ unsigned char smem[];
    const uint32_t sb = smem_u32(smem);
    const int tid = threadIdx.x;
    const int lid = tid & 31;
    const int wid = tid >> 5;
    const int wm  = wid & 3;        // M-warp: rows 32*wm .. +31
    const int wn  = wid >> 2;       // N-warp
    const int e0  = blockIdx.x * MTILE;

    // ---- edge indices -> smem (A region, dead before first A build) ----
    {
        int* s_idx = (int*)smem;
        int e = e0 + (tid & 127);
        int v = 0;
        if (e < E) v = (tid < 128) ? __ldg(src + e) : __ldg(dst + e);
        s_idx[tid] = v;
        __syncthreads();

        // gather h rows (fp32) into padded staging [128][132]
        float* stI = (float*)(smem + STG_I);
        float* stJ = (float*)(smem + STG_J);
        #pragma unroll
        for (int it = 0; it < 32; it++) {
            int lin = it * THREADS + tid;
            int m = lin >> 6, r = lin & 63;
            int isj = r >> 5, q = r & 31;
            int row = s_idx[isj * 128 + m];
            float4 v = __ldg((const float4*)node + (size_t)row * 32 + q);
            float* dp = (isj ? stJ : stI) + m * 132 + q * 4;
            *(float4*)dp = v;
        }
        __syncthreads();
    }

    // ================= layer 1 =================
    float acc[2][16][4];
    #pragma unroll
    for (int mt = 0; mt < 2; mt++)
        #pragma unroll
        for (int nt = 0; nt < 16; nt++)
            #pragma unroll
            for (int j = 0; j < 4; j++) acc[mt][nt][j] = 0.f;

    #pragma unroll 1
    for (int seg = 0; seg < 4; seg++) {
        // build A_seg hi/lo from fp32 staging
        const float* stI = (const float*)(smem + STG_I);
        const float* stJ = (const float*)(smem + STG_J);
        #pragma unroll
        for (int it = 0; it < 32; it++) {
            int lin = it * THREADS + tid;
            int m = lin >> 6, c2 = lin & 63;
            float2 vi = *(const float2*)(stI + m * 132 + 2 * c2);
            float2 vj = *(const float2*)(stJ + m * 132 + 2 * c2);
            float a0, a1;
            if (seg == 0)      { a0 = vi.x; a1 = vi.y; }
            else if (seg == 1) { a0 = vj.x; a1 = vj.y; }
            else if (seg == 2) { a0 = fabsf(vi.x - vj.x); a1 = fabsf(vi.y - vj.y); }
            else               { a0 = vi.x * vj.x;        a1 = vi.y * vj.y; }
            uint32_t h, l;
            split2(a0, a1, h, l);
            *(uint32_t*)(smem + A_HI + m * RS_A + c2 * 4) = h;
            *(uint32_t*)(smem + A_LO + m * RS_A + c2 * 4) = l;
        }
        __syncthreads();

        #pragma unroll 1
        for (int ks = 0; ks < 8; ks++) {
            uint32_t ah[2][4], al[2][4];
            uint32_t ab = sb + A_HI + (wm * 32 + (lid & 15)) * RS_A
                        + ks * 32 + ((lid >> 4) << 4);
            ldsm4(ah[0], ab);
            ldsm4(ah[1], ab + 16 * RS_A);
            ldsm4(al[0], ab + (A_LO - A_HI));
            ldsm4(al[1], ab + (A_LO - A_HI) + 16 * RS_A);

            const unsigned char* bp =
                g_w1p + ((size_t)(((seg << 3) + ks) * 2 + wn) << 13) + (lid << 3);
            #pragma unroll
            for (int np = 0; np < 8; np++) {
                uint2 bh0 = __ldg((const uint2*)(bp + (2 * np) * 512));
                uint2 bh1 = __ldg((const uint2*)(bp + (2 * np + 1) * 512));
                uint2 bl0 = __ldg((const uint2*)(bp + (2 * np) * 512 + 256));
                uint2 bl1 = __ldg((const uint2*)(bp + (2 * np + 1) * 512 + 256));
                hmma(acc[0][2 * np],     ah[0], bh0);
                hmma(acc[0][2 * np + 1], ah[0], bh1);
                hmma(acc[1][2 * np],     ah[1], bh0);
                hmma(acc[1][2 * np + 1], ah[1], bh1);
                hmma(acc[0][2 * np],     al[0], bh0);
                hmma(acc[0][2 * np + 1], al[0], bh1);
                hmma(acc[1][2 * np],     al[1], bh0);
                hmma(acc[1][2 * np + 1], al[1], bh1);
                hmma(acc[0][2 * np],     ah[0], bl0);
                hmma(acc[0][2 * np + 1], ah[0], bl1);
                hmma(acc[1][2 * np],     ah[1], bl0);
                hmma(acc[1][2 * np + 1], ah[1], bl1);
            }
        }
        __syncthreads();
    }

    // ---- epilogue 1: relu(+b1), split, store x1 hi/lo (overwrites staging) ----
    #pragma unroll
    for (int mt = 0; mt < 2; mt++) {
        int r0 = wm * 32 + mt * 16 + (lid >> 2);
        #pragma unroll
        for (int nt = 0; nt < 16; nt++) {
            int c = wn * 128 + nt * 8 + (lid & 3) * 2;
            float bb0 = __ldg(b1v + c), bb1 = __ldg(b1v + c + 1);
            float v0 = fmaxf(acc[mt][nt][0] + bb0, 0.f);
            float v1 = fmaxf(acc[mt][nt][1] + bb1, 0.f);
            float v2 = fmaxf(acc[mt][nt][2] + bb0, 0.f);
            float v3 = fmaxf(acc[mt][nt][3] + bb1, 0.f);
            uint32_t h, l;
            split2(v0, v1, h, l);
            *(uint32_t*)(smem + X_HI + r0 * RS_X + c * 2) = h;
            *(uint32_t*)(smem + X_LO + r0 * RS_X + c * 2) = l;
            split2(v2, v3, h, l);
            *(uint32_t*)(smem + X_HI + (r0 + 8) * RS_X + c * 2) = h;
            *(uint32_t*)(smem + X_LO + (r0 + 8) * RS_X + c * 2) = l;
        }
    }
    __syncthreads();

    // ================= layer 2 =================
    float acc2[2][8][4];
    #pragma unroll
    for (int mt = 0; mt < 2; mt++)
        #pragma unroll
        for (int nt = 0; nt < 8; nt++)
            #pragma unroll
            for (int j = 0; j < 4; j++) acc2[mt][nt][j] = 0.f;

    #pragma unroll 1
    for (int ks = 0; ks < 16; ks++) {
        uint32_t ah[2][4], al[2][4];
        uint32_t ab = sb + X_HI + (wm * 32 + (lid & 15)) * RS_X
                    + ks * 32 + ((lid >> 4) << 4);
        ldsm4(ah[0], ab);
        ldsm4(ah[1], ab + 16 * RS_X);
        ldsm4(al[0], ab + (X_LO - X_HI));
        ldsm4(al[1], ab + (X_LO - X_HI) + 16 * RS_X);

        const unsigned char* bp =
            g_w2p + ((size_t)(ks * 2 + wn) << 12) + (lid << 3);
        #pragma unroll
        for (int np = 0; np < 4; np++) {
            uint2 bh0 = __ldg((const uint2*)(bp + (2 * np) * 512));
            uint2 bh1 = __ldg((const uint2*)(bp + (2 * np + 1) * 512));
            uint2 bl0 = __ldg((const uint2*)(bp + (2 * np) * 512 + 256));
            uint2 bl1 = __ldg((const uint2*)(bp + (2 * np + 1) * 512 + 256));
            hmma(acc2[0][2 * np],     ah[0], bh0);
            hmma(acc2[0][2 * np + 1], ah[0], bh1);
            hmma(acc2[1][2 * np],     ah[1], bh0);
            hmma(acc2[1][2 * np + 1], ah[1], bh1);
            hmma(acc2[0][2 * np],     al[0], bh0);
            hmma(acc2[0][2 * np + 1], al[0], bh1);
            hmma(acc2[1][2 * np],     al[1], bh0);
            hmma(acc2[1][2 * np + 1], al[1], bh1);
            hmma(acc2[0][2 * np],     ah[0], bl0);
            hmma(acc2[0][2 * np + 1], ah[0], bl1);
            hmma(acc2[1][2 * np],     ah[1], bl0);
            hmma(acc2[1][2 * np + 1], ah[1], bl1);
        }
    }

    // ---- epilogue 2: relu(+b2), @W3, reduce, +b3 ----
    float* sred = (float*)smem;   // [2 wn][128 rows][2 outs], A region (dead)
    #pragma unroll
    for (int mt = 0; mt < 2; mt++) {
        int r0 = wm * 32 + mt * 16 + (lid >> 2);
        float s00 = 0.f, s01 = 0.f, s10 = 0.f, s11 = 0.f;
        #pragma unroll
        for (int nt = 0; nt < 8; nt++) {
            int c = wn * 64 + nt * 8 + (lid & 3) * 2;
            float bb0 = __ldg(b2v + c), bb1 = __ldg(b2v + c + 1);
            float x0 = fmaxf(acc2[mt][nt][0] + bb0, 0.f);
            float x1 = fmaxf(acc2[mt][nt][1] + bb1, 0.f);
            float x2 = fmaxf(acc2[mt][nt][2] + bb0, 0.f);
            float x3 = fmaxf(acc2[mt][nt][3] + bb1, 0.f);
            float w00 = __ldg(W3 + c * 2),       w01 = __ldg(W3 + c * 2 + 1);
            float w10 = __ldg(W3 + (c + 1) * 2), w11 = __ldg(W3 + (c + 1) * 2 + 1);
            s00 += x0 * w00 + x1 * w10;
            s01 += x0 * w01 + x1 * w11;
            s10 += x2 * w00 + x3 * w10;
            s11 += x2 * w01 + x3 * w11;
        }
        s00 += __shfl_xor_sync(0xffffffffu, s00, 1);
        s00 += __shfl_xor_sync(0xffffffffu, s00, 2);
        s01 += __shfl_xor_sync(0xffffffffu, s01, 1);
        s01 += __shfl_xor_sync(0xffffffffu, s01, 2);
        s10 += __shfl_xor_sync(0xffffffffu, s10, 1);
        s10 += __shfl_xor_sync(0xffffffffu, s10, 2);
        s11 += __shfl_xor_sync(0xffffffffu, s11, 1);
        s11 += __shfl_xor_sync(0xffffffffu, s11, 2);
        if ((lid & 3) == 0) {
            sred[(wn * 128 + r0) * 2 + 0] = s00;
            sred[(wn * 128 + r0) * 2 + 1] = s01;
            sred[(wn * 128 + r0 + 8) * 2 + 0] = s10;
            sred[(wn * 128 + r0 + 8) * 2 + 1] = s11;
        }
    }
    __syncthreads();

    if (tid < 128) {
        int e = e0 + tid;
        if (e < E) {
            out[2 * e + 0] = sred[tid * 2 + 0] + sred[(128 + tid) * 2 + 0] + __ldg(b3 + 0);
            out[2 * e + 1] = sred[tid * 2 + 1] + sred[(128 + tid) * 2 + 1] + __ldg(b3 + 1);
        }
    }
}

extern "C" void kernel_launch(void* const* d_in, const int* in_sizes, int n_in,
                              void* d_out, int out_size)
{
    const float* node = (const float*)d_in[0];
    const int*   src  = (const int*)  d_in[1];
    const int*   dst  = (const int*)  d_in[2];
    const float* W1   = (const float*)d_in[3];
    const float* b1   = (const float*)d_in[4];
    const float* W2   = (const float*)d_in[5];
    const float* b2   = (const float*)d_in[6];
    const float* W3   = (const float*)d_in[7];
    const float* b3   = (const float*)d_in[8];
    float* out = (float*)d_out;

    const int E = in_sizes[1];

    prep_weights<<<320, 256>>>(W1, W2);

    cudaFuncSetAttribute(linker_hmma_kernel,
                         cudaFuncAttributeMaxDynamicSharedMemorySize, SMEM_BYTES);
    const int grid = (E + MTILE - 1) / MTILE;
    linker_hmma_kernel<<<grid, THREADS, SMEM_BYTES>>>(
        node, src, dst, b1, b2, W3, b3, out, E);
}

// round 7
// speedup vs baseline: 4.2765x; 1.1061x over previous
#include <cuda_runtime.h>
#include <cuda_bf16.h>
#include <math.h>
#include <stdint.h>

// EntityLinker via bf16 split-precision mma.sync (HMMA fallback path, base sm_103).
//
// Round-7 changes vs round-6 (1314us, tensor=59%):
//  - 512 threads, 16 warps in 8M x 2N grid (16 rows/warp): 4 warps/SMSP to
//    hide B-fragment L2 latency; accumulators halve -> fits 128-reg cap.
//  - h_i/h_j gathered+split DIRECTLY into the seg0/seg1 A tiles; |diff|/prod
//    built by one in-place transform (reconstruct fp32 = hi+lo). No fp32
//    staging, no per-seg rebuild phases. smem 205KB -> 140KB.
//
// Precision: x = x_hi(bf16) + x_lo(bf16 residual); 3 MMA terms
// (Ah@Bh + Al@Bh + Ah@Bl), fp32 accumulate inside mma.sync.

#define THREADS 512
#define MTILE 128

// smem layout (bytes)
#define RS_A   272u            // 128 bf16 + 8 pad (row stride; LDSM conflict-free)
#define S0H    0u              // seg0/2 A hi [128 x 128] bf16
#define S0L    34816u          // seg0/2 A lo
#define S1H    69632u          // seg1/3 A hi
#define S1L    104448u         // seg1/3 A lo
#define RS_X   528u            // 256 bf16 + 8 pad
#define X_HI   0u              // layer2 A hi [128 x 256] (aliases S0, dead)
#define X_LO   69632u          // layer2 A lo (aliases S1)
#define IDX_OFF 139264u
#define SMEM_BYTES 140288

// packed weights: W1 4seg x 8ks x 2wn x 16nt x 2part x 32lane x 8B = 512KB
//                 W2 16ks x 2wn x 8nt x 2part x 32lane x 8B = 128KB
__device__ __align__(256) unsigned char g_w1p[524288];
__device__ __align__(256) unsigned char g_w2p[131072];

// ---------------- helpers ----------------

__device__ __forceinline__ uint32_t smem_u32(const void* p) {
    uint32_t a;
    asm("{ .reg .u64 t; cvta.to.shared.u64 t, %1; cvt.u32.u64 %0, t; }"
        : "=r"(a) : "l"(p));
    return a;
}

__device__ __forceinline__ void split2(float a, float b, uint32_t& h, uint32_t& l) {
    __nv_bfloat162 hh = __floats2bfloat162_rn(a, b);
    h = *reinterpret_cast<uint32_t*>(&hh);
    __nv_bfloat162 ll = __floats2bfloat162_rn(a - __bfloat162float(hh.x),
                                              b - __bfloat162float(hh.y));
    l = *reinterpret_cast<uint32_t*>(&ll);
}

__device__ __forceinline__ void ldsm4(uint32_t* r, uint32_t addr) {
    asm volatile("ldmatrix.sync.aligned.m8n8.x4.shared.b16 {%0,%1,%2,%3}, [%4];"
                 : "=r"(r[0]), "=r"(r[1]), "=r"(r[2]), "=r"(r[3]) : "r"(addr));
}

__device__ __forceinline__ void hmma(float* d, const uint32_t* a, uint2 b) {
    asm volatile(
        "mma.sync.aligned.m16n8k16.row.col.f32.bf16.bf16.f32 "
        "{%0,%1,%2,%3}, {%4,%5,%6,%7}, {%8,%9}, {%0,%1,%2,%3};"
        : "+f"(d[0]), "+f"(d[1]), "+f"(d[2]), "+f"(d[3])
        : "r"(a[0]), "r"(a[1]), "r"(a[2]), "r"(a[3]), "r"(b.x), "r"(b.y));
}

// ---------------- prep: pack W1/W2 fragment-major, bf16 hi/lo ----------------

__global__ void prep_weights(const float* __restrict__ W1,
                             const float* __restrict__ W2) {
    int t = blockIdx.x * blockDim.x + threadIdx.x;
    if (t < 65536) {
        int reg  = t & 1;
        int lane = (t >> 1) & 31;
        int site = t >> 6;
        int nt   = site & 15;
        int rest = site >> 4;           // (seg*8+ks)*2+wn
        int wn   = rest & 1;
        int ks   = (rest >> 1) & 7;
        int seg  = rest >> 4;
        int n  = wn * 128 + nt * 8 + (lane >> 2);
        int k0 = seg * 128 + ks * 16 + (lane & 3) * 2 + reg * 8;
        float w0 = W1[k0 * 256 + n];
        float w1 = W1[(k0 + 1) * 256 + n];
        uint32_t h, l;
        split2(w0, w1, h, l);
        size_t base = (size_t)site * 512 + lane * 8 + reg * 4;
        *(uint32_t*)(g_w1p + base)       = h;
        *(uint32_t*)(g_w1p + base + 256) = l;
    } else if (t < 65536 + 16384) {
        int u = t - 65536;
        int reg  = u & 1;
        int lane = (u >> 1) & 31;
        int site = u >> 6;              // (ks*2+wn)*8+nt
        int nt   = site & 7;
        int rest = site >> 3;
        int wn   = rest & 1;
        int ks   = rest >> 1;
        int n  = wn * 64 + nt * 8 + (lane >> 2);
        int k0 = ks * 16 + (lane & 3) * 2 + reg * 8;
        float w0 = W2[k0 * 128 + n];
        float w1 = W2[(k0 + 1) * 128 + n];
        uint32_t h, l;
        split2(w0, w1, h, l);
        size_t base = (size_t)site * 512 + lane * 8 + reg * 4;
        *(uint32_t*)(g_w2p + base)       = h;
        *(uint32_t*)(g_w2p + base + 256) = l;
    }
}

// ---------------- main kernel ----------------

__global__ void __launch_bounds__(THREADS, 1)
linker_hmma_kernel(const float* __restrict__ node,
                   const int* __restrict__ src, const int* __restrict__ dst,
                   const float* __restrict__ b1v, const float* __restrict__ b2v,
                   const float* __restrict__ W3, const float* __restrict__ b3,
                   float* __restrict__ out, int E)
{
    extern __shared__ unsigned char smem[];
    const uint32_t sb = smem_u32(smem);
    const int tid = threadIdx.x;
    const int lid = tid & 31;
    const int wid = tid >> 5;
    const int wm  = wid & 7;        // M-warp: rows 16*wm .. +15
    const int wn  = wid >> 3;       // N-warp (0/1)
    const int e0  = blockIdx.x * MTILE;

    // ---- edge indices ----
    int* s_idx = (int*)(smem + IDX_OFF);
    if (tid < 256) {
        int e = e0 + (tid & 127);
        int v = 0;
        if (e < E) v = (tid < 128) ? __ldg(src + e) : __ldg(dst + e);
        s_idx[tid] = v;
    }
    __syncthreads();

    // ---- gather + bf16-split straight into seg0/seg1 A tiles ----
    #pragma unroll
    for (int it = 0; it < 16; it++) {
        int lin = it * THREADS + tid;
        int m = lin >> 6, r = lin & 63;
        int isj = r >> 5, q = r & 31;
        int row = s_idx[isj * 128 + m];
        float4 v = __ldg((const float4*)node + (size_t)row * 32 + q);
        uint32_t h01, l01, h23, l23;
        split2(v.x, v.y, h01, l01);
        split2(v.z, v.w, h23, l23);
        uint32_t off = (isj ? S1H : S0H) + m * RS_A + q * 8;
        *(uint2*)(smem + off)         = make_uint2(h01, h23);
        *(uint2*)(smem + off + 34816) = make_uint2(l01, l23);
    }
    __syncthreads();

    // ================= layer 1 =================
    float acc[16][4];
    #pragma unroll
    for (int nt = 0; nt < 16; nt++)
        #pragma unroll
        for (int j = 0; j < 4; j++) acc[nt][j] = 0.f;

    #pragma unroll 1
    for (int seg = 0; seg < 4; seg++) {
        if (seg == 2) {
            // in-place: S0 <- |h_i - h_j| (split), S1 <- h_i * h_j (split)
            __syncthreads();
            #pragma unroll
            for (int it = 0; it < 16; it++) {
                int lin = it * THREADS + tid;
                int m = lin >> 6, c2 = lin & 63;
                uint32_t off = m * RS_A + c2 * 4;
                __nv_bfloat162 ih = *(__nv_bfloat162*)(smem + S0H + off);
                __nv_bfloat162 il = *(__nv_bfloat162*)(smem + S0L + off);
                __nv_bfloat162 jh = *(__nv_bfloat162*)(smem + S1H + off);
                __nv_bfloat162 jl = *(__nv_bfloat162*)(smem + S1L + off);
                float fi0 = __bfloat162float(ih.x) + __bfloat162float(il.x);
                float fi1 = __bfloat162float(ih.y) + __bfloat162float(il.y);
                float fj0 = __bfloat162float(jh.x) + __bfloat162float(jl.x);
                float fj1 = __bfloat162float(jh.y) + __bfloat162float(jl.y);
                uint32_t h, l;
                split2(fabsf(fi0 - fj0), fabsf(fi1 - fj1), h, l);
                *(uint32_t*)(smem + S0H + off) = h;
                *(uint32_t*)(smem + S0L + off) = l;
                split2(fi0 * fj0, fi1 * fj1, h, l);
                *(uint32_t*)(smem + S1H + off) = h;
                *(uint32_t*)(smem + S1L + off) = l;
            }
            __syncthreads();
        }
        const uint32_t abase = (seg & 1) ? S1H : S0H;

        #pragma unroll 1
        for (int ks = 0; ks < 8; ks++) {
            uint32_t ah[4], al[4];
            uint32_t ab = sb + abase + (wm * 16 + (lid & 15)) * RS_A
                        + ks * 32 + ((lid >> 4) << 4);
            ldsm4(ah, ab);
            ldsm4(al, ab + 34816);

            const unsigned char* bp =
                g_w1p + ((size_t)(((seg << 3) + ks) * 2 + wn) << 13) + (lid << 3);
            #pragma unroll
            for (int np = 0; np < 8; np++) {
                uint2 bh0 = __ldg((const uint2*)(bp + (2 * np) * 512));
                uint2 bh1 = __ldg((const uint2*)(bp + (2 * np + 1) * 512));
                uint2 bl0 = __ldg((const uint2*)(bp + (2 * np) * 512 + 256));
                uint2 bl1 = __ldg((const uint2*)(bp + (2 * np + 1) * 512 + 256));
                hmma(acc[2 * np],     ah, bh0);
                hmma(acc[2 * np + 1], ah, bh1);
                hmma(acc[2 * np],     al, bh0);
                hmma(acc[2 * np + 1], al, bh1);
                hmma(acc[2 * np],     ah, bl0);
                hmma(acc[2 * np + 1], ah, bl1);
            }
        }
    }
    __syncthreads();   // all ldsm of S0/S1 done before X overwrites them

    // ---- epilogue 1: relu(+b1), split, store x1 hi/lo ----
    {
        int r0 = wm * 16 + (lid >> 2);
        #pragma unroll
        for (int nt = 0; nt < 16; nt++) {
            int c = wn * 128 + nt * 8 + (lid & 3) * 2;
            float bb0 = __ldg(b1v + c), bb1 = __ldg(b1v + c + 1);
            float v0 = fmaxf(acc[nt][0] + bb0, 0.f);
            float v1 = fmaxf(acc[nt][1] + bb1, 0.f);
            float v2 = fmaxf(acc[nt][2] + bb0, 0.f);
            float v3 = fmaxf(acc[nt][3] + bb1, 0.f);
            uint32_t h, l;
            split2(v0, v1, h, l);
            *(uint32_t*)(smem + X_HI + r0 * RS_X + c * 2) = h;
            *(uint32_t*)(smem + X_LO + r0 * RS_X + c * 2) = l;
            split2(v2, v3, h, l);
            *(uint32_t*)(smem + X_HI + (r0 + 8) * RS_X + c * 2) = h;
            *(uint32_t*)(smem + X_LO + (r0 + 8) * RS_X + c * 2) = l;
        }
    }
    __syncthreads();

    // ================= layer 2 =================
    float acc2[8][4];
    #pragma unroll
    for (int nt = 0; nt < 8; nt++)
        #pragma unroll
        for (int j = 0; j < 4; j++) acc2[nt][j] = 0.f;

    #pragma unroll 1
    for (int ks = 0; ks < 16; ks++) {
        uint32_t ah[4], al[4];
        uint32_t ab = sb + X_HI + (wm * 16 + (lid & 15)) * RS_X
                    + ks * 32 + ((lid >> 4) << 4);
        ldsm4(ah, ab);
        ldsm4(al, ab + (X_LO - X_HI));

        const unsigned char* bp =
            g_w2p + ((size_t)(ks * 2 + wn) << 12) + (lid << 3);
        #pragma unroll
        for (int np = 0; np < 4; np++) {
            uint2 bh0 = __ldg((const uint2*)(bp + (2 * np) * 512));
            uint2 bh1 = __ldg((const uint2*)(bp + (2 * np + 1) * 512));
            uint2 bl0 = __ldg((const uint2*)(bp + (2 * np) * 512 + 256));
            uint2 bl1 = __ldg((const uint2*)(bp + (2 * np + 1) * 512 + 256));
            hmma(acc2[2 * np],     ah, bh0);
            hmma(acc2[2 * np + 1], ah, bh1);
            hmma(acc2[2 * np],     al, bh0);
            hmma(acc2[2 * np + 1], al, bh1);
            hmma(acc2[2 * np],     ah, bl0);
            hmma(acc2[2 * np + 1], ah, bl1);
        }
    }
    __syncthreads();   // X reads done before sred overwrites region

    // ---- epilogue 2: relu(+b2), @W3, reduce, +b3 ----
    float* sred = (float*)smem;    // [2 wn][128 rows][2 outs]
    {
        int r0 = wm * 16 + (lid >> 2);
        float s00 = 0.f, s01 = 0.f, s10 = 0.f, s11 = 0.f;
        #pragma unroll
        for (int nt = 0; nt < 8; nt++) {
            int c = wn * 64 + nt * 8 + (lid & 3) * 2;
            float bb0 = __ldg(b2v + c), bb1 = __ldg(b2v + c + 1);
            float x0 = fmaxf(acc2[nt][0] + bb0, 0.f);
            float x1 = fmaxf(acc2[nt][1] + bb1, 0.f);
            float x2 = fmaxf(acc2[nt][2] + bb0, 0.f);
            float x3 = fmaxf(acc2[nt][3] + bb1, 0.f);
            float w00 = __ldg(W3 + c * 2),       w01 = __ldg(W3 + c * 2 + 1);
            float w10 = __ldg(W3 + (c + 1) * 2), w11 = __ldg(W3 + (c + 1) * 2 + 1);
            s00 += x0 * w00 + x1 * w10;
            s01 += x0 * w01 + x1 * w11;
            s10 += x2 * w00 + x3 * w10;
            s11 += x2 * w01 + x3 * w11;
        }
        s00 += __shfl_xor_sync(0xffffffffu, s00, 1);
        s00 += __shfl_xor_sync(0xffffffffu, s00, 2);
        s01 += __shfl_xor_sync(0xffffffffu, s01, 1);
        s01 += __shfl_xor_sync(0xffffffffu, s01, 2);
        s10 += __shfl_xor_sync(0xffffffffu, s10, 1);
        s10 += __shfl_xor_sync(0xffffffffu, s10, 2);
        s11 += __shfl_xor_sync(0xffffffffu, s11, 1);
        s11 += __shfl_xor_sync(0xffffffffu, s11, 2);
        if ((lid & 3) == 0) {
            sred[(wn * 128 + r0) * 2 + 0] = s00;
            sred[(wn * 128 + r0) * 2 + 1] = s01;
            sred[(wn * 128 + r0 + 8) * 2 + 0] = s10;
            sred[(wn * 128 + r0 + 8) * 2 + 1] = s11;
        }
    }
    __syncthreads();

    if (tid < 128) {
        int e = e0 + tid;
        if (e < E) {
            out[2 * e + 0] = sred[tid * 2 + 0] + sred[(128 + tid) * 2 + 0] + __ldg(b3 + 0);
            out[2 * e + 1] = sred[tid * 2 + 1] + sred[(128 + tid) * 2 + 1] + __ldg(b3 + 1);
        }
    }
}

extern "C" void kernel_launch(void* const* d_in, const int* in_sizes, int n_in,
                              void* d_out, int out_size)
{
    const float* node = (const float*)d_in[0];
    const int*   src  = (const int*)  d_in[1];
    const int*   dst  = (const int*)  d_in[2];
    const float* W1   = (const float*)d_in[3];
    const float* b1   = (const float*)d_in[4];
    const float* W2   = (const float*)d_in[5];
    const float* b2   = (const float*)d_in[6];
    const float* W3   = (const float*)d_in[7];
    const float* b3   = (const float*)d_in[8];
    float* out = (float*)d_out;

    const int E = in_sizes[1];

    prep_weights<<<320, 256>>>(W1, W2);

    cudaFuncSetAttribute(linker_hmma_kernel,
                         cudaFuncAttributeMaxDynamicSharedMemorySize, SMEM_BYTES);
    const int grid = (E + MTILE - 1) / MTILE;
    linker_hmma_kernel<<<grid, THREADS, SMEM_BYTES>>>(
        node, src, dst, b1, b2, W3, b3, out, E);
}